// round 6
// baseline (speedup 1.0000x reference)
#include <cuda_runtime.h>
#include <cuda_bf16.h>
#include <cstdint>

#define BATCH 32
#define FEAT  1024
#define PROJ  256
#define NSUP  8192
#define NCLS  1000
#define KEXP  (FEAT * 3)   // 3072 expanded bf16 per row

// ---- scratch (no allocations allowed; __device__ globals) ----
__device__ float g_xq[BATCH * PROJ];
__device__ float g_logits[BATCH * NSUP];         // 1 MB
__device__ int   g_sy_is64;
__device__ __nv_bfloat16 g_wt_e[PROJ * KEXP];    // 1.5 MB: W^T 3-slot expanded

__device__ __forceinline__ uint32_t smem_u32(const void* p) {
    uint32_t a;
    asm("{ .reg .u64 t; cvta.to.shared.u64 t, %1; cvt.u32.u64 %0, t; }"
        : "=r"(a) : "l"(p));
    return a;
}

// ---------------------------------------------------------------------------
// K0: detect int64 vs int32 sy
// ---------------------------------------------------------------------------
__global__ void k_detect(const unsigned* __restrict__ w) {
    __shared__ int nz;
    if (threadIdx.x == 0) nz = 0;
    __syncthreads();
    int f = 0;
    for (int i = threadIdx.x; i < 4096; i += 256)
        if (w[2 * i + 1] != 0u) f = 1;
    if (f) atomicOr(&nz, 1);
    __syncthreads();
    if (threadIdx.x == 0) g_sy_is64 = (nz == 0) ? 1 : 0;
}

// zero g_logits (exactly 65536 float4 = 1 MB)
__global__ void k_zero_lg(void) {
    ((float4*)g_logits)[blockIdx.x * 256 + threadIdx.x] =
        make_float4(0.f, 0.f, 0.f, 0.f);
}

// ---------------------------------------------------------------------------
// K_wt: W[1024][256] -> g_wt_e[256][3072], per orig k the slots (bh, bh, bl)
// ---------------------------------------------------------------------------
__global__ void k_wt(const float* __restrict__ W) {
    __shared__ float t[32][33];
    __shared__ __align__(16) __nv_bfloat16 ex[32 * 96];
    const int kb = blockIdx.x * 32, nb = blockIdx.y * 32;
    const int tx = threadIdx.x & 31, ty = threadIdx.x >> 5;  // ty 0..7
#pragma unroll
    for (int r = 0; r < 4; r++)
        t[ty + r * 8][tx] = W[(size_t)(kb + ty + r * 8) * PROJ + nb + tx];
    __syncthreads();
#pragma unroll
    for (int r = 0; r < 4; r++) {
        int nl = ty + r * 8;
        float a = t[tx][nl];
        __nv_bfloat16 h = __float2bfloat16(a);
        __nv_bfloat16 l = __float2bfloat16(a - __bfloat162float(h));
        ex[nl * 96 + 3 * tx + 0] = h;
        ex[nl * 96 + 3 * tx + 1] = h;
        ex[nl * 96 + 3 * tx + 2] = l;
    }
    __syncthreads();
    const uint4* ex4 = (const uint4*)ex;
    uint4* out4 = (uint4*)g_wt_e;
#pragma unroll
    for (int it = 0; it < 2; it++) {
        int idx = it * 256 + threadIdx.x;  // 0..383 (32 rows x 12 uint4)
        if (idx < 384) {
            int row = idx / 12, u = idx % 12;
            out4[(size_t)(nb + row) * (KEXP / 8) + blockIdx.x * 12 + u] =
                ex4[row * 12 + u];
        }
    }
}

// ---------------------------------------------------------------------------
// K1: xq = x @ W (32 x 256). grid (32 b, 8 p-chunks), 256 thr = 32 p x 8 kslc.
// ---------------------------------------------------------------------------
__global__ void k_xq2(const float* __restrict__ x, const float* __restrict__ W) {
    __shared__ float red[8][33];
    const int b = blockIdx.x, pc = blockIdx.y;
    const int lane = threadIdx.x & 31, ks = threadIdx.x >> 5;
    const int p = pc * 32 + lane;
    float a0 = 0.f, a1 = 0.f, a2 = 0.f, a3 = 0.f;
    const float* xr = x + b * FEAT + ks * 128;
    const float* wr = W + (size_t)(ks * 128) * PROJ + p;
#pragma unroll 8
    for (int k = 0; k < 128; k += 4) {
        a0 = fmaf(xr[k + 0], wr[(k + 0) * PROJ], a0);
        a1 = fmaf(xr[k + 1], wr[(k + 1) * PROJ], a1);
        a2 = fmaf(xr[k + 2], wr[(k + 2) * PROJ], a2);
        a3 = fmaf(xr[k + 3], wr[(k + 3) * PROJ], a3);
    }
    red[ks][lane] = (a0 + a1) + (a2 + a3);
    __syncthreads();
    if (ks == 0) {
        float s = 0.f;
#pragma unroll
        for (int q = 0; q < 8; q++) s += red[q][lane];
        g_xq[b * PROJ + p] = s;
    }
}

// ---------------------------------------------------------------------------
// K2: sxp tile GEMM (HMMA, 3-slot K-expansion) + fused logits epilogue.
// 512 threads / 16 warps (4M x 4N), warp tile 32x32, CTA tile 128x128.
// Grid (64, 2). 4 warps/SMSP for latency hiding.
// ---------------------------------------------------------------------------
#define PITCHB 112
#define STGB   (128 * PITCHB)          // 14336 B per stage matrix
#define TS_OFF    0
#define TS_PITCH  132                  // floats
#define XQT_OFF   67584                // 128*132*4
#define XQT_PITCH 36
#define SSQ_OFF   86016                // XQT_OFF + 128*36*4
#define DYNB      86528

__global__ void __launch_bounds__(512, 1)
k_sxp_hmma(const float* __restrict__ sx) {
    extern __shared__ __align__(16) char dyn[];

    const int tid  = threadIdx.x;
    const int lane = tid & 31;
    const int wid  = tid >> 5;       // 0..15
    const int wm   = wid & 3;        // M block (32 rows)
    const int wn   = wid >> 2;       // N block (32 cols)
    const int bs   = blockIdx.x * 128;
    const int bn   = blockIdx.y * 128;

    const uint32_t sbase = smem_u32(dyn);
    const uint32_t a_u32[2] = {sbase, sbase + STGB};
    const uint32_t b_u32[2] = {sbase + 2 * STGB, sbase + 3 * STGB};
    uint2* a_st[2] = {(uint2*)dyn, (uint2*)(dyn + STGB)};
    uint4* b_st[2] = {(uint4*)(dyn + 2 * STGB), (uint4*)(dyn + 3 * STGB)};

    // A: one float4 per thread per chunk
    const int lr0 = tid >> 2, lq0 = tid & 3;
    const float* Abase = sx + (size_t)bs * FEAT;

    // B: 768 uint4 per chunk, 2 iters (second partial)
    const int bidx1 = 512 + tid;
    const int brow0 = tid / 6,   bu0 = tid % 6;
    const int brow1 = bidx1 / 6, bu1 = bidx1 % 6;
    const bool bpred1 = (bidx1 < 768);
    const uint4* gwt4 = (const uint4*)g_wt_e;

    float c[2][4][4];
#pragma unroll
    for (int t = 0; t < 2; t++)
#pragma unroll
        for (int n = 0; n < 4; n++)
#pragma unroll
            for (int e = 0; e < 4; e++) c[t][n][e] = 0.f;

    const int grp  = lane >> 3;
    const int rsel = lane & 7;
    const int a_row_off = ((grp & 1) << 3) + rsel;
    const int a_u_off   = (grp >> 1) & 1;
    const int b_row_off = ((grp >> 1) << 3) + rsel;
    const int b_u_off   = grp & 1;

    auto pk = [](__nv_bfloat16 a, __nv_bfloat16 b) -> uint32_t {
        __nv_bfloat162 t = __halves2bfloat162(a, b);
        return *(uint32_t*)&t;
    };
    auto expand = [&pk](float4 v, uint2* o) {
        __nv_bfloat16 h0 = __float2bfloat16(v.x), h1 = __float2bfloat16(v.y);
        __nv_bfloat16 h2 = __float2bfloat16(v.z), h3 = __float2bfloat16(v.w);
        __nv_bfloat16 l0 = __float2bfloat16(v.x - __bfloat162float(h0));
        __nv_bfloat16 l1 = __float2bfloat16(v.y - __bfloat162float(h1));
        __nv_bfloat16 l2 = __float2bfloat16(v.z - __bfloat162float(h2));
        __nv_bfloat16 l3 = __float2bfloat16(v.w - __bfloat162float(h3));
        o[0] = make_uint2(pk(h0, l0), pk(h0, h1));
        o[1] = make_uint2(pk(l1, h1), pk(h2, l2));
        o[2] = make_uint2(pk(h2, h3), pk(l3, h3));
    };

    // ---- prologue: chunk 0 ----
    {
        float4 av = *(const float4*)(Abase + (size_t)lr0 * FEAT + lq0 * 4);
        uint2 e0[3];
        expand(av, e0);
#pragma unroll
        for (int m = 0; m < 3; m++)
            a_st[0][lr0 * 14 + lq0 * 3 + m] = e0[m];
        b_st[0][brow0 * 7 + bu0] = gwt4[(size_t)(bn + brow0) * (KEXP / 8) + bu0];
        if (bpred1)
            b_st[0][brow1 * 7 + bu1] = gwt4[(size_t)(bn + brow1) * (KEXP / 8) + bu1];
    }
    __syncthreads();

    for (int ch = 0; ch < 64; ch++) {
        const int s = ch & 1;
        float4 av;
        uint4  bv0, bv1;
        if (ch < 63) {
            const int k0 = (ch + 1) * 16;
            av  = *(const float4*)(Abase + (size_t)lr0 * FEAT + k0 + lq0 * 4);
            bv0 = gwt4[(size_t)(bn + brow0) * (KEXP / 8) + (ch + 1) * 6 + bu0];
            if (bpred1)
                bv1 = gwt4[(size_t)(bn + brow1) * (KEXP / 8) + (ch + 1) * 6 + bu1];
        }

        // ---- compute on stage s: 3 ksteps ----
#pragma unroll
        for (int ks = 0; ks < 3; ks++) {
            uint32_t af[2][4];
#pragma unroll
            for (int t = 0; t < 2; t++) {
                int row = wm * 32 + t * 16 + a_row_off;
                uint32_t addr = a_u32[s] + (uint32_t)(row * PITCHB + (2 * ks + a_u_off) * 16);
                asm volatile(
                    "ldmatrix.sync.aligned.m8n8.x4.shared.b16 {%0,%1,%2,%3}, [%4];"
                    : "=r"(af[t][0]), "=r"(af[t][1]), "=r"(af[t][2]), "=r"(af[t][3])
                    : "r"(addr));
            }
            uint32_t bf[2][4];
#pragma unroll
            for (int np = 0; np < 2; np++) {
                int row = wn * 32 + np * 16 + b_row_off;
                uint32_t addr = b_u32[s] + (uint32_t)(row * PITCHB + (2 * ks + b_u_off) * 16);
                asm volatile(
                    "ldmatrix.sync.aligned.m8n8.x4.shared.b16 {%0,%1,%2,%3}, [%4];"
                    : "=r"(bf[np][0]), "=r"(bf[np][1]), "=r"(bf[np][2]), "=r"(bf[np][3])
                    : "r"(addr));
            }
#pragma unroll
            for (int t = 0; t < 2; t++)
#pragma unroll
                for (int nf = 0; nf < 4; nf++) {
                    uint32_t b0 = bf[nf >> 1][(nf & 1) * 2 + 0];
                    uint32_t b1 = bf[nf >> 1][(nf & 1) * 2 + 1];
                    asm volatile(
                        "mma.sync.aligned.m16n8k16.row.col.f32.bf16.bf16.f32 "
                        "{%0,%1,%2,%3}, {%4,%5,%6,%7}, {%8,%9}, {%0,%1,%2,%3};"
                        : "+f"(c[t][nf][0]), "+f"(c[t][nf][1]),
                          "+f"(c[t][nf][2]), "+f"(c[t][nf][3])
                        : "r"(af[t][0]), "r"(af[t][1]), "r"(af[t][2]), "r"(af[t][3]),
                          "r"(b0), "r"(b1));
                }
        }

        if (ch < 63) {
            const int ns = s ^ 1;
            uint2 e0[3];
            expand(av, e0);
            __syncthreads();
#pragma unroll
            for (int m = 0; m < 3; m++)
                a_st[ns][lr0 * 14 + lq0 * 3 + m] = e0[m];
            b_st[ns][brow0 * 7 + bu0] = bv0;
            if (bpred1) b_st[ns][brow1 * 7 + bu1] = bv1;
            __syncthreads();
        }
    }

    // ================= fused logits epilogue =================
    __syncthreads();   // done reading stage smem; reuse it
    float* Ts   = (float*)(dyn + TS_OFF);    // [128][132] sxp tile
    float* xqT  = (float*)(dyn + XQT_OFF);   // [128][36]  xq half, transposed
    float* ssqh = (float*)(dyn + SSQ_OFF);   // [128]

    // spill fragments: Ts[j = local support][k = local proj]
#pragma unroll
    for (int t = 0; t < 2; t++) {
        int r0 = wm * 32 + t * 16 + (lane >> 2);
        int cl = wn * 32 + 2 * (lane & 3);
#pragma unroll
        for (int nf = 0; nf < 4; nf++) {
            *(float2*)&Ts[r0 * TS_PITCH + cl + nf * 8] =
                make_float2(c[t][nf][0], c[t][nf][1]);
            *(float2*)&Ts[(r0 + 8) * TS_PITCH + cl + nf * 8] =
                make_float2(c[t][nf][2], c[t][nf][3]);
        }
    }
    // load xq half transposed: xqT[k][b]
    for (int i = tid; i < 32 * 128; i += 512) {
        int b = i & 31, k = i >> 5;
        xqT[k * XQT_PITCH + b] = g_xq[b * PROJ + bn + k];
    }
    __syncthreads();

    // ssq_half[j]
    if (tid < 128) {
        float s = 0.f;
        const float4* row = (const float4*)&Ts[tid * TS_PITCH];
#pragma unroll
        for (int q = 0; q < 32; q++) {
            float4 v = row[q];
            s += v.x * v.x + v.y * v.y + v.z * v.z + v.w * v.w;
        }
        ssqh[tid] = s;
    }
    __syncthreads();

    // partial logits: 4 j x 2 b per thread
    {
        const int j0 = (tid >> 4) * 4;        // 0..124
        const int b0 = (tid & 15) * 2;        // 0..30
        float acc[4][2];
#pragma unroll
        for (int a = 0; a < 4; a++) { acc[a][0] = 0.f; acc[a][1] = 0.f; }

        for (int k = 0; k < 128; k += 4) {
            float2 xv[4];
#pragma unroll
            for (int kk = 0; kk < 4; kk++)
                xv[kk] = *(const float2*)&xqT[(k + kk) * XQT_PITCH + b0];
#pragma unroll
            for (int jj = 0; jj < 4; jj++) {
                float4 tv = *(const float4*)&Ts[(j0 + jj) * TS_PITCH + k];
                float tk[4] = {tv.x, tv.y, tv.z, tv.w};
#pragma unroll
                for (int kk = 0; kk < 4; kk++) {
                    acc[jj][0] = fmaf(tk[kk], xv[kk].x, acc[jj][0]);
                    acc[jj][1] = fmaf(tk[kk], xv[kk].y, acc[jj][1]);
                }
            }
        }
#pragma unroll
        for (int jj = 0; jj < 4; jj++) {
            float sq = ssqh[j0 + jj];
            atomicAdd(&g_logits[(size_t)(b0 + 0) * NSUP + bs + j0 + jj],
                      2.f * acc[jj][0] - sq);
            atomicAdd(&g_logits[(size_t)(b0 + 1) * NSUP + bs + j0 + jj],
                      2.f * acc[jj][1] - sq);
        }
    }
}

// ---------------------------------------------------------------------------
// K5: per-row softmax + class scatter + log
// ---------------------------------------------------------------------------
__global__ void __launch_bounds__(1024) k_out(const int* __restrict__ syw,
                                              float* __restrict__ out) {
    const int b = blockIdx.x;
    __shared__ float red[32];
    __shared__ float cls[NCLS];
    const int tid  = threadIdx.x;
    const int warp = tid >> 5, lane = tid & 31;

    for (int c = tid; c < NCLS; c += 1024) cls[c] = 0.f;

    const float* lr = g_logits + (size_t)b * NSUP;
    float l[8];
    float m = -3.4e38f;
#pragma unroll
    for (int q = 0; q < 8; q++) {
        l[q] = lr[q * 1024 + tid];
        m = fmaxf(m, l[q]);
    }
#pragma unroll
    for (int o = 16; o; o >>= 1) m = fmaxf(m, __shfl_xor_sync(0xffffffffu, m, o));
    if (lane == 0) red[warp] = m;
    __syncthreads();
    if (warp == 0) {
        float v = red[lane];
#pragma unroll
        for (int o = 16; o; o >>= 1) v = fmaxf(v, __shfl_xor_sync(0xffffffffu, v, o));
        if (lane == 0) red[0] = v;
    }
    __syncthreads();
    m = red[0];
    __syncthreads();

    float e[8];
    float s = 0.f;
#pragma unroll
    for (int q = 0; q < 8; q++) {
        e[q] = expf(l[q] - m);
        s += e[q];
    }
#pragma unroll
    for (int o = 16; o; o >>= 1) s += __shfl_xor_sync(0xffffffffu, s, o);
    if (lane == 0) red[warp] = s;
    __syncthreads();
    if (warp == 0) {
        float v = red[lane];
#pragma unroll
        for (int o = 16; o; o >>= 1) v += __shfl_xor_sync(0xffffffffu, v, o);
        if (lane == 0) red[0] = v;
    }
    __syncthreads();
    const float invZ = 1.f / red[0];
    const int is64 = g_sy_is64;

#pragma unroll
    for (int q = 0; q < 8; q++) {
        int j = q * 1024 + tid;
        int cidx = is64 ? syw[2 * j] : syw[j];
        atomicAdd(&cls[cidx], e[q]);
    }
    __syncthreads();
    for (int c = tid; c < NCLS; c += 1024)
        out[b * NCLS + c] = logf(cls[c] * invZ + 1e-12f);
}

// ---------------------------------------------------------------------------
extern "C" void kernel_launch(void* const* d_in, const int* in_sizes, int n_in,
                              void* d_out, int out_size) {
    const float* x = nullptr;
    const float* sx = nullptr;
    const float* W = nullptr;
    const void*  sy = nullptr;
    for (int i = 0; i < n_in; i++) {
        switch (in_sizes[i]) {
            case BATCH * FEAT: x  = (const float*)d_in[i]; break;
            case NSUP * FEAT:  sx = (const float*)d_in[i]; break;
            case FEAT * PROJ:  W  = (const float*)d_in[i]; break;
            case NSUP:         sy = d_in[i];               break;
            default: break;
        }
    }
    float* out = (float*)d_out;

    static int smem_set = 0;
    if (!smem_set) {
        cudaFuncSetAttribute(k_sxp_hmma,
                             cudaFuncAttributeMaxDynamicSharedMemorySize, DYNB);
        smem_set = 1;
    }

    k_detect<<<1, 256>>>((const unsigned*)sy);
    k_zero_lg<<<256, 256>>>();
    k_wt<<<dim3(32, 8), 256>>>(W);
    k_xq2<<<dim3(32, 8), 256>>>(x, W);
    k_sxp_hmma<<<dim3(64, 2), 512, DYNB>>>(sx);
    k_out<<<BATCH, 1024>>>((const int*)sy, out);
}

// round 7
// speedup vs baseline: 1.2171x; 1.2171x over previous
#include <cuda_runtime.h>
#include <cuda_fp16.h>
#include <cstdint>

#define BATCH 32
#define FEAT  1024
#define PROJ  256
#define NSUP  8192
#define NCLS  1000

// ---- scratch (no allocations allowed; __device__ globals) ----
__device__ float g_xq[BATCH * PROJ];
__device__ float g_lh[2 * BATCH * NSUP];         // 2 MB: per-proj-half logits
__device__ int   g_sy_is64;
__device__ __half2 g_wt2[PROJ * FEAT];           // 1 MB: W^T (h,l) fp16 pairs

__device__ __forceinline__ uint32_t smem_u32(const void* p) {
    uint32_t a;
    asm("{ .reg .u64 t; cvta.to.shared.u64 t, %1; cvt.u32.u64 %0, t; }"
        : "=r"(a) : "l"(p));
    return a;
}

// ---------------------------------------------------------------------------
// K0: detect int64 vs int32 sy
// ---------------------------------------------------------------------------
__global__ void k_detect(const unsigned* __restrict__ w) {
    __shared__ int nz;
    if (threadIdx.x == 0) nz = 0;
    __syncthreads();
    int f = 0;
    for (int i = threadIdx.x; i < 4096; i += 256)
        if (w[2 * i + 1] != 0u) f = 1;
    if (f) atomicOr(&nz, 1);
    __syncthreads();
    if (threadIdx.x == 0) g_sy_is64 = (nz == 0) ? 1 : 0;
}

// ---------------------------------------------------------------------------
// K_wt: W[1024][256] -> g_wt2[256][1024] fp16 (h,l) pairs, transposed
// ---------------------------------------------------------------------------
__global__ void k_wt(const float* __restrict__ W) {
    __shared__ float t[32][33];
    const int kb = blockIdx.x * 32, nb = blockIdx.y * 32;
    const int tx = threadIdx.x & 31, ty = threadIdx.x >> 5;  // ty 0..7
#pragma unroll
    for (int r = 0; r < 4; r++)
        t[ty + r * 8][tx] = W[(size_t)(kb + ty + r * 8) * PROJ + nb + tx];
    __syncthreads();
#pragma unroll
    for (int r = 0; r < 4; r++) {
        int n = nb + ty + r * 8;
        float a = t[tx][ty + r * 8];
        __half h = __float2half_rn(a);
        __half l = __float2half_rn(a - __half2float(h));
        g_wt2[(size_t)n * FEAT + kb + tx] = __halves2half2(h, l);
    }
}

// ---------------------------------------------------------------------------
// K1: xq = x @ W (32 x 256). grid (32 b, 8 p-chunks), 256 thr = 32 p x 8 kslc.
// ---------------------------------------------------------------------------
__global__ void k_xq2(const float* __restrict__ x, const float* __restrict__ W) {
    __shared__ float red[8][33];
    const int b = blockIdx.x, pc = blockIdx.y;
    const int lane = threadIdx.x & 31, ks = threadIdx.x >> 5;
    const int p = pc * 32 + lane;
    float a0 = 0.f, a1 = 0.f, a2 = 0.f, a3 = 0.f;
    const float* xr = x + b * FEAT + ks * 128;
    const float* wr = W + (size_t)(ks * 128) * PROJ + p;
#pragma unroll 8
    for (int k = 0; k < 128; k += 4) {
        a0 = fmaf(xr[k + 0], wr[(k + 0) * PROJ], a0);
        a1 = fmaf(xr[k + 1], wr[(k + 1) * PROJ], a1);
        a2 = fmaf(xr[k + 2], wr[(k + 2) * PROJ], a2);
        a3 = fmaf(xr[k + 3], wr[(k + 3) * PROJ], a3);
    }
    red[ks][lane] = (a0 + a1) + (a2 + a3);
    __syncthreads();
    if (ks == 0) {
        float s = 0.f;
#pragma unroll
        for (int q = 0; q < 8; q++) s += red[q][lane];
        g_xq[b * PROJ + p] = s;
    }
}

// ---------------------------------------------------------------------------
// K2: sxp tile GEMM (HMMA fp16, 2-slot K-doubling K'=2048) + fused logits.
// 256 thr / 8 warps (4M x 2N), warp tile 32x64, CTA 128x128, grid (64, 2).
// Chunk = 16 orig k = 32 fp16. Smem pitch 80 B -> conflict-free ldmatrix.
// Epilogue writes partial logits (2*dot - ssq_half) to its own half-buffer.
// ---------------------------------------------------------------------------
#define PITCHH 40                     // halfs per smem row (80 B)
#define STGB   (128 * 80)             // 10240 B per stage matrix
#define TS_PITCH  132
#define XQT_OFF   67584               // 128*132*4
#define XQT_PITCH 36
#define SSQ_OFF   86016               // XQT_OFF + 128*36*4
#define DYNB      86528

__global__ void __launch_bounds__(256, 1)
k_sxp_hmma(const float* __restrict__ sx) {
    extern __shared__ __align__(16) char dyn[];

    const int tid  = threadIdx.x;
    const int lane = tid & 31;
    const int wid  = tid >> 5;
    const int wm   = wid & 3;        // M block (32 rows)
    const int wn   = wid >> 2;       // N block (64 cols)
    const int bs   = blockIdx.x * 128;
    const int bn   = blockIdx.y * 128;
    const int half = blockIdx.y;

    const uint32_t sbase = smem_u32(dyn);
    const uint32_t a_u32[2] = {sbase, sbase + STGB};
    const uint32_t b_u32[2] = {sbase + 2 * STGB, sbase + 3 * STGB};
    uint4* a_st[2] = {(uint4*)dyn, (uint4*)(dyn + STGB)};
    uint4* b_st[2] = {(uint4*)(dyn + 2 * STGB), (uint4*)(dyn + 3 * STGB)};

    // load coords: i = p*256+tid -> row = i>>2, q = i&3 (4 orig k per uint4)
    const int lr0 = tid >> 2,         lq0 = tid & 3;
    const int lr1 = (256 + tid) >> 2, lq1 = (256 + tid) & 3;
    const float* Abase = sx + (size_t)bs * FEAT;
    const uint4* gwt4 = (const uint4*)g_wt2;   // row stride: 256 uint4

    float c[2][8][4];
#pragma unroll
    for (int t = 0; t < 2; t++)
#pragma unroll
        for (int n = 0; n < 8; n++)
#pragma unroll
            for (int e = 0; e < 4; e++) c[t][n][e] = 0.f;

    const int grp  = lane >> 3;
    const int rsel = lane & 7;
    const int a_row_off = ((grp & 1) << 3) + rsel;
    const int a_u_off   = (grp >> 1) & 1;
    const int b_row_off = ((grp >> 1) << 3) + rsel;
    const int b_u_off   = grp & 1;

    // float4 (4 orig k) -> 8 fp16 (h,l per k) = uint4
    auto expand = [](float4 v) -> uint4 {
        __half h0 = __float2half_rn(v.x), h1 = __float2half_rn(v.y);
        __half h2 = __float2half_rn(v.z), h3 = __float2half_rn(v.w);
        __half2 p0 = __halves2half2(h0, __float2half_rn(v.x - __half2float(h0)));
        __half2 p1 = __halves2half2(h1, __float2half_rn(v.y - __half2float(h1)));
        __half2 p2 = __halves2half2(h2, __float2half_rn(v.z - __half2float(h2)));
        __half2 p3 = __halves2half2(h3, __float2half_rn(v.w - __half2float(h3)));
        return make_uint4(*(uint32_t*)&p0, *(uint32_t*)&p1,
                          *(uint32_t*)&p2, *(uint32_t*)&p3);
    };

    // ---- prologue: chunk 0 ----
    {
        float4 av0 = *(const float4*)(Abase + (size_t)lr0 * FEAT + lq0 * 4);
        float4 av1 = *(const float4*)(Abase + (size_t)lr1 * FEAT + lq1 * 4);
        a_st[0][lr0 * 5 + lq0] = expand(av0);
        a_st[0][lr1 * 5 + lq1] = expand(av1);
        b_st[0][lr0 * 5 + lq0] = gwt4[(size_t)(bn + lr0) * 256 + lq0];
        b_st[0][lr1 * 5 + lq1] = gwt4[(size_t)(bn + lr1) * 256 + lq1];
    }
    __syncthreads();

    for (int ch = 0; ch < 64; ch++) {
        const int s = ch & 1;
        float4 av0, av1;
        uint4  bv0, bv1;
        if (ch < 63) {
            const int k0 = (ch + 1) * 16;
            av0 = *(const float4*)(Abase + (size_t)lr0 * FEAT + k0 + lq0 * 4);
            av1 = *(const float4*)(Abase + (size_t)lr1 * FEAT + k0 + lq1 * 4);
            bv0 = gwt4[(size_t)(bn + lr0) * 256 + (ch + 1) * 4 + lq0];
            bv1 = gwt4[(size_t)(bn + lr1) * 256 + (ch + 1) * 4 + lq1];
        }

        // ---- compute on stage s: 2 ksteps of 16 expanded k ----
#pragma unroll
        for (int ks = 0; ks < 2; ks++) {
            uint32_t af[2][4];
#pragma unroll
            for (int t = 0; t < 2; t++) {
                int row = wm * 32 + t * 16 + a_row_off;
                uint32_t addr = a_u32[s] + (uint32_t)(row * 80 + (2 * ks + a_u_off) * 16);
                asm volatile(
                    "ldmatrix.sync.aligned.m8n8.x4.shared.b16 {%0,%1,%2,%3}, [%4];"
                    : "=r"(af[t][0]), "=r"(af[t][1]), "=r"(af[t][2]), "=r"(af[t][3])
                    : "r"(addr));
            }
            uint32_t bf[4][4];
#pragma unroll
            for (int np = 0; np < 4; np++) {
                int row = wn * 64 + np * 16 + b_row_off;
                uint32_t addr = b_u32[s] + (uint32_t)(row * 80 + (2 * ks + b_u_off) * 16);
                asm volatile(
                    "ldmatrix.sync.aligned.m8n8.x4.shared.b16 {%0,%1,%2,%3}, [%4];"
                    : "=r"(bf[np][0]), "=r"(bf[np][1]), "=r"(bf[np][2]), "=r"(bf[np][3])
                    : "r"(addr));
            }
#pragma unroll
            for (int t = 0; t < 2; t++)
#pragma unroll
                for (int nf = 0; nf < 8; nf++) {
                    uint32_t b0 = bf[nf >> 1][(nf & 1) * 2 + 0];
                    uint32_t b1 = bf[nf >> 1][(nf & 1) * 2 + 1];
                    asm volatile(
                        "mma.sync.aligned.m16n8k16.row.col.f32.f16.f16.f32 "
                        "{%0,%1,%2,%3}, {%4,%5,%6,%7}, {%8,%9}, {%0,%1,%2,%3};"
                        : "+f"(c[t][nf][0]), "+f"(c[t][nf][1]),
                          "+f"(c[t][nf][2]), "+f"(c[t][nf][3])
                        : "r"(af[t][0]), "r"(af[t][1]), "r"(af[t][2]), "r"(af[t][3]),
                          "r"(b0), "r"(b1));
                }
        }

        if (ch < 63) {
            const int ns = s ^ 1;
            uint4 ea = expand(av0), eb = expand(av1);
            __syncthreads();
            a_st[ns][lr0 * 5 + lq0] = ea;
            a_st[ns][lr1 * 5 + lq1] = eb;
            b_st[ns][lr0 * 5 + lq0] = bv0;
            b_st[ns][lr1 * 5 + lq1] = bv1;
            __syncthreads();
        }
    }

    // ================= fused logits epilogue =================
    __syncthreads();   // done reading stage smem; reuse it
    float* Ts   = (float*)dyn;               // [128][132] sxp tile
    float* xqT  = (float*)(dyn + XQT_OFF);   // [128][36]  xq half, transposed
    float* ssqh = (float*)(dyn + SSQ_OFF);   // [128]

    // spill fragments: Ts[j = local support][k = local proj]
#pragma unroll
    for (int t = 0; t < 2; t++) {
        int r0 = wm * 32 + t * 16 + (lane >> 2);
        int cl = wn * 64 + 2 * (lane & 3);
#pragma unroll
        for (int nf = 0; nf < 8; nf++) {
            *(float2*)&Ts[r0 * TS_PITCH + cl + nf * 8] =
                make_float2(c[t][nf][0], c[t][nf][1]);
            *(float2*)&Ts[(r0 + 8) * TS_PITCH + cl + nf * 8] =
                make_float2(c[t][nf][2], c[t][nf][3]);
        }
    }
    // load xq half transposed: xqT[k][b]
    for (int i = tid; i < 32 * 128; i += 256) {
        int b = i & 31, k = i >> 5;
        xqT[k * XQT_PITCH + b] = g_xq[b * PROJ + bn + k];
    }
    __syncthreads();

    // ssq_half[j]
    if (tid < 128) {
        float s = 0.f;
        const float4* row = (const float4*)&Ts[tid * TS_PITCH];
#pragma unroll
        for (int q = 0; q < 32; q++) {
            float4 v = row[q];
            s += v.x * v.x + v.y * v.y + v.z * v.z + v.w * v.w;
        }
        ssqh[tid] = s;
    }
    __syncthreads();

    // partial logits: 4 j x 4 b per thread; j contiguous per lane for
    // coalesced float4 stores.
    {
        const int j0 = (tid & 31) * 4;        // 0..124
        const int b0 = (tid >> 5) * 4;        // 0..28
        float acc[4][4];
#pragma unroll
        for (int a = 0; a < 4; a++)
#pragma unroll
            for (int b = 0; b < 4; b++) acc[a][b] = 0.f;

        for (int k = 0; k < 128; k += 4) {
            float4 xv[4];
#pragma unroll
            for (int kk = 0; kk < 4; kk++)
                xv[kk] = *(const float4*)&xqT[(k + kk) * XQT_PITCH + b0];
#pragma unroll
            for (int jj = 0; jj < 4; jj++) {
                float4 tv = *(const float4*)&Ts[(j0 + jj) * TS_PITCH + k];
                float tk[4] = {tv.x, tv.y, tv.z, tv.w};
#pragma unroll
                for (int kk = 0; kk < 4; kk++) {
                    acc[jj][0] = fmaf(tk[kk], xv[kk].x, acc[jj][0]);
                    acc[jj][1] = fmaf(tk[kk], xv[kk].y, acc[jj][1]);
                    acc[jj][2] = fmaf(tk[kk], xv[kk].z, acc[jj][2]);
                    acc[jj][3] = fmaf(tk[kk], xv[kk].w, acc[jj][3]);
                }
            }
        }
        float4 sq = *(const float4*)&ssqh[j0];
        float sqa[4] = {sq.x, sq.y, sq.z, sq.w};
#pragma unroll
        for (int bb = 0; bb < 4; bb++) {
            float4 o;
            o.x = 2.f * acc[0][bb] - sqa[0];
            o.y = 2.f * acc[1][bb] - sqa[1];
            o.z = 2.f * acc[2][bb] - sqa[2];
            o.w = 2.f * acc[3][bb] - sqa[3];
            *(float4*)&g_lh[((size_t)half * BATCH + b0 + bb) * NSUP + bs + j0] = o;
        }
    }
}

// ---------------------------------------------------------------------------
// K5: per-row softmax + class scatter + log (sums the two proj-half logits)
// ---------------------------------------------------------------------------
__global__ void __launch_bounds__(1024) k_out(const int* __restrict__ syw,
                                              float* __restrict__ out) {
    const int b = blockIdx.x;
    __shared__ float red[32];
    __shared__ float cls[NCLS];
    const int tid  = threadIdx.x;
    const int warp = tid >> 5, lane = tid & 31;

    for (int c = tid; c < NCLS; c += 1024) cls[c] = 0.f;

    const float* lr0 = g_lh + (size_t)b * NSUP;
    const float* lr1 = g_lh + (size_t)(BATCH + b) * NSUP;
    float l[8];
    float m = -3.4e38f;
#pragma unroll
    for (int q = 0; q < 8; q++) {
        int j = q * 1024 + tid;
        l[q] = lr0[j] + lr1[j];
        m = fmaxf(m, l[q]);
    }
#pragma unroll
    for (int o = 16; o; o >>= 1) m = fmaxf(m, __shfl_xor_sync(0xffffffffu, m, o));
    if (lane == 0) red[warp] = m;
    __syncthreads();
    if (warp == 0) {
        float v = red[lane];
#pragma unroll
        for (int o = 16; o; o >>= 1) v = fmaxf(v, __shfl_xor_sync(0xffffffffu, v, o));
        if (lane == 0) red[0] = v;
    }
    __syncthreads();
    m = red[0];
    __syncthreads();

    float e[8];
    float s = 0.f;
#pragma unroll
    for (int q = 0; q < 8; q++) {
        e[q] = expf(l[q] - m);
        s += e[q];
    }
#pragma unroll
    for (int o = 16; o; o >>= 1) s += __shfl_xor_sync(0xffffffffu, s, o);
    if (lane == 0) red[warp] = s;
    __syncthreads();
    if (warp == 0) {
        float v = red[lane];
#pragma unroll
        for (int o = 16; o; o >>= 1) v += __shfl_xor_sync(0xffffffffu, v, o);
        if (lane == 0) red[0] = v;
    }
    __syncthreads();
    const float invZ = 1.f / red[0];
    const int is64 = g_sy_is64;

#pragma unroll
    for (int q = 0; q < 8; q++) {
        int j = q * 1024 + tid;
        int cidx = is64 ? syw[2 * j] : syw[j];
        atomicAdd(&cls[cidx], e[q]);
    }
    __syncthreads();
    for (int c = tid; c < NCLS; c += 1024)
        out[b * NCLS + c] = logf(cls[c] * invZ + 1e-12f);
}

// ---------------------------------------------------------------------------
extern "C" void kernel_launch(void* const* d_in, const int* in_sizes, int n_in,
                              void* d_out, int out_size) {
    const float* x = nullptr;
    const float* sx = nullptr;
    const float* W = nullptr;
    const void*  sy = nullptr;
    for (int i = 0; i < n_in; i++) {
        switch (in_sizes[i]) {
            case BATCH * FEAT: x  = (const float*)d_in[i]; break;
            case NSUP * FEAT:  sx = (const float*)d_in[i]; break;
            case FEAT * PROJ:  W  = (const float*)d_in[i]; break;
            case NSUP:         sy = d_in[i];               break;
            default: break;
        }
    }
    float* out = (float*)d_out;

    static int smem_set = 0;
    if (!smem_set) {
        cudaFuncSetAttribute(k_sxp_hmma,
                             cudaFuncAttributeMaxDynamicSharedMemorySize, DYNB);
        smem_set = 1;
    }

    k_detect<<<1, 256>>>((const unsigned*)sy);
    k_wt<<<dim3(32, 8), 256>>>(W);
    k_xq2<<<dim3(32, 8), 256>>>(x, W);
    k_sxp_hmma<<<dim3(64, 2), 256, DYNB>>>(sx);
    k_out<<<BATCH, 1024>>>((const int*)sy, out);
}

// round 8
// speedup vs baseline: 1.5292x; 1.2564x over previous
#include <cuda_runtime.h>
#include <cuda_fp16.h>
#include <cstdint>

#define BATCH 32
#define FEAT  1024
#define PROJ  256
#define NSUP  8192
#define NCLS  1000

// ---- scratch (no allocations allowed; __device__ globals) ----
__device__ float g_xq[BATCH * PROJ];
__device__ float g_lh[2 * BATCH * NSUP];         // 2 MB: per-proj-half logits
__device__ int   g_sy_is64;
// B in mma-fragment order: idx = ks*512 + half*256 + wn*128 + np*32 + lane
// (uint4 each: {slice0-klo, slice0-khi, slice1-klo, slice1-khi} half2 (h,l))
__device__ uint4 g_wfrag[128 * 512];             // 1 MB

__device__ __forceinline__ uint32_t smem_u32(const void* p) {
    uint32_t a;
    asm("{ .reg .u64 t; cvta.to.shared.u64 t, %1; cvt.u32.u64 %0, t; }"
        : "=r"(a) : "l"(p));
    return a;
}

// ---------------------------------------------------------------------------
// K0: detect int64 vs int32 sy
// ---------------------------------------------------------------------------
__global__ void k_detect(const unsigned* __restrict__ w) {
    __shared__ int nz;
    if (threadIdx.x == 0) nz = 0;
    __syncthreads();
    int f = 0;
    for (int i = threadIdx.x; i < 4096; i += 256)
        if (w[2 * i + 1] != 0u) f = 1;
    if (f) atomicOr(&nz, 1);
    __syncthreads();
    if (threadIdx.x == 0) g_sy_is64 = (nz == 0) ? 1 : 0;
}

// ---------------------------------------------------------------------------
// K_wtf: W[1024][256] -> g_wfrag (fp16 h/l pairs in mma B-fragment order)
// ---------------------------------------------------------------------------
__device__ __forceinline__ uint32_t hl_pack(float a) {
    __half h = __float2half_rn(a);
    __half l = __float2half_rn(a - __half2float(h));
    __half2 p = __halves2half2(h, l);
    return *(uint32_t*)&p;
}

__global__ void k_wtf(const float* __restrict__ W) {
    int idx  = blockIdx.x * 256 + threadIdx.x;   // 0..65535
    int lane = idx & 31;
    int np   = (idx >> 5) & 3;
    int wn   = (idx >> 7) & 1;
    int hb   = (idx >> 8) & 1;
    int ks   = idx >> 9;                          // 0..127
    int n0   = hb * 128 + wn * 64 + np * 16 + (lane >> 2);
    int k0   = ks * 8 + (lane & 3);
    uint4 r;
    r.x = hl_pack(W[(size_t)k0 * PROJ + n0]);
    r.y = hl_pack(W[(size_t)(k0 + 4) * PROJ + n0]);
    r.z = hl_pack(W[(size_t)k0 * PROJ + n0 + 8]);
    r.w = hl_pack(W[(size_t)(k0 + 4) * PROJ + n0 + 8]);
    g_wfrag[idx] = r;
}

// ---------------------------------------------------------------------------
// K1: xq = x @ W (32 x 256). grid (32 b, 8 p-chunks), 256 thr = 32 p x 8 kslc.
// ---------------------------------------------------------------------------
__global__ void k_xq2(const float* __restrict__ x, const float* __restrict__ W) {
    __shared__ float red[8][33];
    const int b = blockIdx.x, pc = blockIdx.y;
    const int lane = threadIdx.x & 31, ks = threadIdx.x >> 5;
    const int p = pc * 32 + lane;
    float a0 = 0.f, a1 = 0.f, a2 = 0.f, a3 = 0.f;
    const float* xr = x + b * FEAT + ks * 128;
    const float* wr = W + (size_t)(ks * 128) * PROJ + p;
#pragma unroll 8
    for (int k = 0; k < 128; k += 4) {
        a0 = fmaf(xr[k + 0], wr[(k + 0) * PROJ], a0);
        a1 = fmaf(xr[k + 1], wr[(k + 1) * PROJ], a1);
        a2 = fmaf(xr[k + 2], wr[(k + 2) * PROJ], a2);
        a3 = fmaf(xr[k + 3], wr[(k + 3) * PROJ], a3);
    }
    red[ks][lane] = (a0 + a1) + (a2 + a3);
    __syncthreads();
    if (ks == 0) {
        float s = 0.f;
#pragma unroll
        for (int q = 0; q < 8; q++) s += red[q][lane];
        g_xq[b * PROJ + p] = s;
    }
}

// ---------------------------------------------------------------------------
// K2: sxp GEMM (HMMA fp16 2-slot K-doubling) + fused logits epilogue.
// A via smem (pitch 80 B, conflict-free ldmatrix); B via direct LDG.128 of
// precomputed fragments (no STS/LDSM for B). 256 thr, warp 32x64, grid (64,2).
// ---------------------------------------------------------------------------
#define STGB   (128 * 80)             // 10240 B per A stage
#define TS_PITCH  132
#define XQT_OFF   67584               // 128*132*4
#define XQT_PITCH 36
#define SSQ_OFF   86016               // XQT_OFF + 128*36*4
#define DYNB      86528

__global__ void __launch_bounds__(256, 1)
k_sxp_hmma(const float* __restrict__ sx) {
    extern __shared__ __align__(16) char dyn[];

    const int tid  = threadIdx.x;
    const int lane = tid & 31;
    const int wid  = tid >> 5;
    const int wm   = wid & 3;        // M block (32 rows)
    const int wn   = wid >> 2;       // N block (64 cols)
    const int bs   = blockIdx.x * 128;
    const int bn   = blockIdx.y * 128;
    const int hb   = blockIdx.y;

    const uint32_t sbase = smem_u32(dyn);
    const uint32_t a_u32[2] = {sbase, sbase + STGB};
    uint4* a_st[2] = {(uint4*)dyn, (uint4*)(dyn + STGB)};

    // A load coords: i = p*256+tid -> row = i>>2, q = i&3
    const int lr0 = tid >> 2,         lq0 = tid & 3;
    const int lr1 = (256 + tid) >> 2, lq1 = (256 + tid) & 3;
    const float* Abase = sx + (size_t)bs * FEAT;

    // B fragment pointer: idx = ks*512 + hb*256 + wn*128 + np*32 + lane
    const uint4* bbase = g_wfrag + hb * 256 + wn * 128 + lane;

    float c[2][8][4];
#pragma unroll
    for (int t = 0; t < 2; t++)
#pragma unroll
        for (int n = 0; n < 8; n++)
#pragma unroll
            for (int e = 0; e < 4; e++) c[t][n][e] = 0.f;

    const int grp  = lane >> 3;
    const int rsel = lane & 7;
    const int a_row_off = ((grp & 1) << 3) + rsel;
    const int a_u_off   = (grp >> 1) & 1;

    auto expand = [](float4 v) -> uint4 {
        __half h0 = __float2half_rn(v.x), h1 = __float2half_rn(v.y);
        __half h2 = __float2half_rn(v.z), h3 = __float2half_rn(v.w);
        __half2 p0 = __halves2half2(h0, __float2half_rn(v.x - __half2float(h0)));
        __half2 p1 = __halves2half2(h1, __float2half_rn(v.y - __half2float(h1)));
        __half2 p2 = __halves2half2(h2, __float2half_rn(v.z - __half2float(h2)));
        __half2 p3 = __halves2half2(h3, __float2half_rn(v.w - __half2float(h3)));
        return make_uint4(*(uint32_t*)&p0, *(uint32_t*)&p1,
                          *(uint32_t*)&p2, *(uint32_t*)&p3);
    };

    uint4 bcur[2][4];

    // ---- prologue: chunk 0 ----
    {
        float4 av0 = *(const float4*)(Abase + (size_t)lr0 * FEAT + lq0 * 4);
        float4 av1 = *(const float4*)(Abase + (size_t)lr1 * FEAT + lq1 * 4);
        a_st[0][lr0 * 5 + lq0] = expand(av0);
        a_st[0][lr1 * 5 + lq1] = expand(av1);
#pragma unroll
        for (int ks = 0; ks < 2; ks++)
#pragma unroll
            for (int np = 0; np < 4; np++)
                bcur[ks][np] = bbase[ks * 512 + np * 32];
    }
    __syncthreads();

#pragma unroll 2
    for (int ch = 0; ch < 64; ch++) {
        const int s = ch & 1;
        float4 av0, av1;
        uint4  bnx[2][4];
        if (ch < 63) {
            const int k0 = (ch + 1) * 16;
            av0 = *(const float4*)(Abase + (size_t)lr0 * FEAT + k0 + lq0 * 4);
            av1 = *(const float4*)(Abase + (size_t)lr1 * FEAT + k0 + lq1 * 4);
#pragma unroll
            for (int ks = 0; ks < 2; ks++)
#pragma unroll
                for (int np = 0; np < 4; np++)
                    bnx[ks][np] = bbase[(2 * (ch + 1) + ks) * 512 + np * 32];
        }

        // ---- compute on stage s: 2 ksteps of 16 expanded k ----
#pragma unroll
        for (int ks = 0; ks < 2; ks++) {
            uint32_t af[2][4];
#pragma unroll
            for (int t = 0; t < 2; t++) {
                int row = wm * 32 + t * 16 + a_row_off;
                uint32_t addr = a_u32[s] + (uint32_t)(row * 80 + (2 * ks + a_u_off) * 16);
                asm volatile(
                    "ldmatrix.sync.aligned.m8n8.x4.shared.b16 {%0,%1,%2,%3}, [%4];"
                    : "=r"(af[t][0]), "=r"(af[t][1]), "=r"(af[t][2]), "=r"(af[t][3])
                    : "r"(addr));
            }
#pragma unroll
            for (int t = 0; t < 2; t++)
#pragma unroll
                for (int nf = 0; nf < 8; nf++) {
                    const uint4& bq = bcur[ks][nf >> 1];
                    uint32_t b0 = (nf & 1) ? bq.z : bq.x;
                    uint32_t b1 = (nf & 1) ? bq.w : bq.y;
                    asm volatile(
                        "mma.sync.aligned.m16n8k16.row.col.f32.f16.f16.f32 "
                        "{%0,%1,%2,%3}, {%4,%5,%6,%7}, {%8,%9}, {%0,%1,%2,%3};"
                        : "+f"(c[t][nf][0]), "+f"(c[t][nf][1]),
                          "+f"(c[t][nf][2]), "+f"(c[t][nf][3])
                        : "r"(af[t][0]), "r"(af[t][1]), "r"(af[t][2]), "r"(af[t][3]),
                          "r"(b0), "r"(b1));
                }
        }

        if (ch < 63) {
            const int ns = s ^ 1;
            uint4 ea = expand(av0), eb = expand(av1);
            __syncthreads();
            a_st[ns][lr0 * 5 + lq0] = ea;
            a_st[ns][lr1 * 5 + lq1] = eb;
#pragma unroll
            for (int ks = 0; ks < 2; ks++)
#pragma unroll
                for (int np = 0; np < 4; np++)
                    bcur[ks][np] = bnx[ks][np];
            __syncthreads();
        }
    }

    // ================= fused logits epilogue =================
    __syncthreads();   // done reading stage smem; reuse it
    float* Ts   = (float*)dyn;               // [128][132] sxp tile
    float* xqT  = (float*)(dyn + XQT_OFF);   // [128][36]  xq half, transposed
    float* ssqh = (float*)(dyn + SSQ_OFF);   // [128]

    // spill fragments: Ts[j = local support][k = local proj]
#pragma unroll
    for (int t = 0; t < 2; t++) {
        int r0 = wm * 32 + t * 16 + (lane >> 2);
        int cl = wn * 64 + 2 * (lane & 3);
#pragma unroll
        for (int nf = 0; nf < 8; nf++) {
            *(float2*)&Ts[r0 * TS_PITCH + cl + nf * 8] =
                make_float2(c[t][nf][0], c[t][nf][1]);
            *(float2*)&Ts[(r0 + 8) * TS_PITCH + cl + nf * 8] =
                make_float2(c[t][nf][2], c[t][nf][3]);
        }
    }
    // load xq half transposed: xqT[k][b]
    for (int i = tid; i < 32 * 128; i += 256) {
        int b = i & 31, k = i >> 5;
        xqT[k * XQT_PITCH + b] = g_xq[b * PROJ + bn + k];
    }
    __syncthreads();

    // ssq_half[j]
    if (tid < 128) {
        float s = 0.f;
        const float4* row = (const float4*)&Ts[tid * TS_PITCH];
#pragma unroll
        for (int q = 0; q < 32; q++) {
            float4 v = row[q];
            s += v.x * v.x + v.y * v.y + v.z * v.z + v.w * v.w;
        }
        ssqh[tid] = s;
    }
    __syncthreads();

    // partial logits: 4 j x 4 b per thread; coalesced float4 stores along j
    {
        const int j0 = (tid & 31) * 4;        // 0..124
        const int b0 = (tid >> 5) * 4;        // 0..28
        float acc[4][4];
#pragma unroll
        for (int a = 0; a < 4; a++)
#pragma unroll
            for (int b = 0; b < 4; b++) acc[a][b] = 0.f;

        for (int k = 0; k < 128; k += 4) {
            float4 xv[4];
#pragma unroll
            for (int kk = 0; kk < 4; kk++)
                xv[kk] = *(const float4*)&xqT[(k + kk) * XQT_PITCH + b0];
#pragma unroll
            for (int jj = 0; jj < 4; jj++) {
                float4 tv = *(const float4*)&Ts[(j0 + jj) * TS_PITCH + k];
                float tk[4] = {tv.x, tv.y, tv.z, tv.w};
#pragma unroll
                for (int kk = 0; kk < 4; kk++) {
                    acc[jj][0] = fmaf(tk[kk], xv[kk].x, acc[jj][0]);
                    acc[jj][1] = fmaf(tk[kk], xv[kk].y, acc[jj][1]);
                    acc[jj][2] = fmaf(tk[kk], xv[kk].z, acc[jj][2]);
                    acc[jj][3] = fmaf(tk[kk], xv[kk].w, acc[jj][3]);
                }
            }
        }
        float4 sq = *(const float4*)&ssqh[j0];
        float sqa[4] = {sq.x, sq.y, sq.z, sq.w};
#pragma unroll
        for (int bb = 0; bb < 4; bb++) {
            float4 o;
            o.x = 2.f * acc[0][bb] - sqa[0];
            o.y = 2.f * acc[1][bb] - sqa[1];
            o.z = 2.f * acc[2][bb] - sqa[2];
            o.w = 2.f * acc[3][bb] - sqa[3];
            *(float4*)&g_lh[((size_t)hb * BATCH + b0 + bb) * NSUP + bs + j0] = o;
        }
    }
}

// ---------------------------------------------------------------------------
// K5: per-row softmax + class scatter + log (sums the two proj-half logits)
// ---------------------------------------------------------------------------
__global__ void __launch_bounds__(1024) k_out(const int* __restrict__ syw,
                                              float* __restrict__ out) {
    const int b = blockIdx.x;
    __shared__ float red[32];
    __shared__ float cls[NCLS];
    const int tid  = threadIdx.x;
    const int warp = tid >> 5, lane = tid & 31;

    for (int c = tid; c < NCLS; c += 1024) cls[c] = 0.f;

    const float* lr0 = g_lh + (size_t)b * NSUP;
    const float* lr1 = g_lh + (size_t)(BATCH + b) * NSUP;
    float l[8];
    float m = -3.4e38f;
#pragma unroll
    for (int q = 0; q < 8; q++) {
        int j = q * 1024 + tid;
        l[q] = lr0[j] + lr1[j];
        m = fmaxf(m, l[q]);
    }
#pragma unroll
    for (int o = 16; o; o >>= 1) m = fmaxf(m, __shfl_xor_sync(0xffffffffu, m, o));
    if (lane == 0) red[warp] = m;
    __syncthreads();
    if (warp == 0) {
        float v = red[lane];
#pragma unroll
        for (int o = 16; o; o >>= 1) v = fmaxf(v, __shfl_xor_sync(0xffffffffu, v, o));
        if (lane == 0) red[0] = v;
    }
    __syncthreads();
    m = red[0];
    __syncthreads();

    float e[8];
    float s = 0.f;
#pragma unroll
    for (int q = 0; q < 8; q++) {
        e[q] = expf(l[q] - m);
        s += e[q];
    }
#pragma unroll
    for (int o = 16; o; o >>= 1) s += __shfl_xor_sync(0xffffffffu, s, o);
    if (lane == 0) red[warp] = s;
    __syncthreads();
    if (warp == 0) {
        float v = red[lane];
#pragma unroll
        for (int o = 16; o; o >>= 1) v += __shfl_xor_sync(0xffffffffu, v, o);
        if (lane == 0) red[0] = v;
    }
    __syncthreads();
    const float invZ = 1.f / red[0];
    const int is64 = g_sy_is64;

#pragma unroll
    for (int q = 0; q < 8; q++) {
        int j = q * 1024 + tid;
        int cidx = is64 ? syw[2 * j] : syw[j];
        atomicAdd(&cls[cidx], e[q]);
    }
    __syncthreads();
    for (int c = tid; c < NCLS; c += 1024)
        out[b * NCLS + c] = logf(cls[c] * invZ + 1e-12f);
}

// ---------------------------------------------------------------------------
extern "C" void kernel_launch(void* const* d_in, const int* in_sizes, int n_in,
                              void* d_out, int out_size) {
    const float* x = nullptr;
    const float* sx = nullptr;
    const float* W = nullptr;
    const void*  sy = nullptr;
    for (int i = 0; i < n_in; i++) {
        switch (in_sizes[i]) {
            case BATCH * FEAT: x  = (const float*)d_in[i]; break;
            case NSUP * FEAT:  sx = (const float*)d_in[i]; break;
            case FEAT * PROJ:  W  = (const float*)d_in[i]; break;
            case NSUP:         sy = d_in[i];               break;
            default: break;
        }
    }
    float* out = (float*)d_out;

    static int smem_set = 0;
    if (!smem_set) {
        cudaFuncSetAttribute(k_sxp_hmma,
                             cudaFuncAttributeMaxDynamicSharedMemorySize, DYNB);
        smem_set = 1;
    }

    k_detect<<<1, 256>>>((const unsigned*)sy);
    k_wtf<<<256, 256>>>(W);
    k_xq2<<<dim3(32, 8), 256>>>(x, W);
    k_sxp_hmma<<<dim3(64, 2), 256, DYNB>>>(sx);
    k_out<<<BATCH, 1024>>>((const int*)sy, out);
}